// round 10
// baseline (speedup 1.0000x reference)
#include <cuda_runtime.h>
#include <cuda_fp16.h>
#include <cstdint>

#define M_DIM 8192
#define K_DIM 4096
#define N_DIM 11008
#define NG_DIM 32
#define KSTR 4224                 /* K + 128 ext columns */

#define TILE_M 128
#define TILE_N 128
#define NT (N_DIM / TILE_N) /* 86 */
#define MT (M_DIM / TILE_M) /* 64 */
#define NTHREADS 256

// ---------------- scratch (static device arrays: allocation-free) ----------------
__device__ __half g_A[(size_t)M_DIM * KSTR];      // fp16(x) + 128 ext cols (S hi/hi/lo/lo)
__device__ float  g_S[NG_DIM * M_DIM];            // group sums of rounded x
__device__ uint32_t g_sc[(size_t)NG_DIM * N_DIM]; // lo16 = fp16(s), hi16 = fp16(-1024*s)
__device__ __half g_BextT[(size_t)N_DIM * 128];   // per-n ext B row: [zs_hi, zs_lo, zs_hi, zs_lo]

// ---------------- smem layout ----------------
#define ROW_STRIDE 272
#define A_BUF_BYTES (TILE_M * ROW_STRIDE)        /* 34816 */
#define OFF_A0 0
#define OFF_A1 A_BUF_BYTES
#define OFF_W  (2 * A_BUF_BYTES)                 /* 69632: 2 x 8192 packed W */
#define OFF_S  (OFF_W + 16384)                   /* 86016: 2 x 512B (s,c) slots */
#define SMEM_BYTES (OFF_S + 1024)                /* 87040 */

// ---------------- helpers ----------------
__device__ __forceinline__ uint32_t smem_u32(const void* p) {
    uint32_t a;
    asm("{ .reg .u64 t; cvta.to.shared.u64 t, %1; cvt.u32.u64 %0, t; }" : "=r"(a) : "l"(p));
    return a;
}

#define CP_ASYNC16(dst, src) \
    asm volatile("cp.async.cg.shared.global [%0], [%1], 16;" :: "r"(dst), "l"(src))
#define CP_COMMIT() asm volatile("cp.async.commit_group;" ::: "memory")
#define CP_WAIT0()  asm volatile("cp.async.wait_group 0;" ::: "memory")

#define LDSM_X4(r0, r1, r2, r3, addr) \
    asm volatile("ldmatrix.sync.aligned.m8n8.x4.shared.b16 {%0,%1,%2,%3}, [%4];" \
                 : "=r"(r0), "=r"(r1), "=r"(r2), "=r"(r3) : "r"(addr))

#define MMA16816(d, a, b0v, b1v) \
    asm volatile("mma.sync.aligned.m16n8k16.row.col.f32.f16.f16.f32 " \
                 "{%0,%1,%2,%3}, {%4,%5,%6,%7}, {%8,%9}, {%0,%1,%2,%3};" \
                 : "+f"((d)[0]), "+f"((d)[1]), "+f"((d)[2]), "+f"((d)[3]) \
                 : "r"((a)[0]), "r"((a)[1]), "r"((a)[2]), "r"((a)[3]), \
                   "r"(b0v), "r"(b1v))

// ---------------- prep 1: round x to fp16 into g_A + group sums ----------------
__global__ void prep_kernel(const float* __restrict__ x) {
    int gwarp = (blockIdx.x * blockDim.x + threadIdx.x) >> 5;
    int lane  = threadIdx.x & 31;
    if (gwarp >= M_DIM * NG_DIM) return;
    int m = gwarp / NG_DIM;
    int g = gwarp % NG_DIM;
    const float* xr = x + (size_t)m * K_DIM + (size_t)g * 128;
    __half* ar = g_A + (size_t)m * KSTR + (size_t)g * 128;
    float sum = 0.f;
#pragma unroll
    for (int j = 0; j < 4; j++) {
        float v = xr[lane + 32 * j];
        __half hi = __float2half_rn(v);
        ar[lane + 32 * j] = hi;
        sum += __half2float(hi);
    }
#pragma unroll
    for (int o = 16; o > 0; o >>= 1) sum += __shfl_xor_sync(0xFFFFFFFFu, sum, o);
    if (lane == 0) g_S[g * M_DIM + m] = sum;
}

// ---------------- prep 2a: A extension cols (S hi,hi,lo,lo blocks) ----------------
__global__ void prep_ext_kernel() {
    int idx = blockIdx.x * blockDim.x + threadIdx.x;
    if (idx >= M_DIM * NG_DIM) return;
    int m = idx >> 5;
    int g = idx & 31;
    float S = g_S[g * M_DIM + m];
    __half hi = __float2half_rn(S);
    __half lo = __float2half_rn(S - __half2float(hi));
    __half* ar = g_A + (size_t)m * KSTR + 4096;
    ar[g]      = hi;
    ar[32 + g] = hi;
    ar[64 + g] = lo;
    ar[96 + g] = lo;
}

// ---------------- prep 2b: (s, -1024s) table + ext B rows ----------------
__global__ void prep_zs_kernel(const float* __restrict__ scales, const float* __restrict__ zeros) {
    int idx = blockIdx.x * blockDim.x + threadIdx.x;
    if (idx >= NG_DIM * N_DIM) return;
    int g = idx / N_DIM;
    int n = idx - g * N_DIM;
    float s = scales[idx];
    float z = zeros[idx];
    __half sh = __float2half_rn(s);
    __half ch = __hmul(sh, __float2half_rn(-1024.f));   // exact power-of-two scale
    uint16_t su, cu;
    *(__half*)&su = sh; *(__half*)&cu = ch;
    g_sc[idx] = (uint32_t)su | ((uint32_t)cu << 16);

    float zs = -z * s;
    __half hi2 = __float2half_rn(zs);
    __half lo2 = __float2half_rn(zs - __half2float(hi2));
    __half* br = g_BextT + (size_t)n * 128;
    br[g]      = hi2;
    br[32 + g] = lo2;
    br[64 + g] = hi2;
    br[96 + g] = lo2;
}

// ---------------- pipeline pieces ----------------
__device__ __forceinline__ void cp_a(uint32_t abuf, int g, int m0, int tid) {
#pragma unroll
    for (int i = 0; i < 8; i++) {
        int idx = tid + i * NTHREADS;           // 0..2047 16B chunks
        int row = idx >> 4;
        int c   = idx & 15;
        size_t goff = (size_t)(m0 + row) * KSTR + (size_t)g * 128 + (size_t)c * 8;
        CP_ASYNC16(abuf + (uint32_t)row * ROW_STRIDE + (uint32_t)c * 16,
                   (const char*)(g_A + goff));
    }
}

// A extension tile (128 rows x 128 halves)
__device__ __forceinline__ void cp_a_ext(uint32_t abuf, int m0, int tid) {
#pragma unroll
    for (int i = 0; i < 8; i++) {
        int idx = tid + i * NTHREADS;           // 0..2047
        int row = idx >> 4;
        int c   = idx & 15;
        size_t goff = (size_t)(m0 + row) * KSTR + 4096 + (size_t)c * 8;
        CP_ASYNC16(abuf + (uint32_t)row * ROW_STRIDE + (uint32_t)c * 16,
                   (const char*)(g_A + goff));
    }
}

// packed W for group g: 16 kp rows x 128 words, linear 8KB
__device__ __forceinline__ void cp_w(uint32_t wbuf, int g, int n0, int tid,
                                     const int* __restrict__ Wq) {
#pragma unroll
    for (int i = 0; i < 2; i++) {
        int idx = tid + i * NTHREADS;           // 0..511 16B chunks
        int kp  = idx >> 5;
        int cw  = idx & 31;
        CP_ASYNC16(wbuf + (uint32_t)idx * 16,
                   (const char*)(Wq + (size_t)(g * 16 + kp) * N_DIM + n0 + cw * 4));
    }
}

// (s,c) row for group g into slot (128 u32 = 512B)
__device__ __forceinline__ void cp_sc(uint32_t sbase, int slot, int g, int n0, int tid) {
    if (tid < 32)
        CP_ASYNC16(sbase + OFF_S + (uint32_t)slot * 512 + (uint32_t)tid * 16,
                   (const char*)(g_sc + (size_t)g * N_DIM + n0 + tid * 4));
}

// ext B rows into spare A buffer (128 rows x 256B data @272 stride)
__device__ __forceinline__ void cp_b_ext(uint32_t bbuf, int n0, int tid) {
#pragma unroll
    for (int i = 0; i < 8; i++) {
        int a = tid + i * NTHREADS;             // 0..2047
        int row  = a >> 4;
        int part = a & 15;
        CP_ASYNC16(bbuf + (uint32_t)row * ROW_STRIDE + (uint32_t)part * 16,
                   (const char*)(g_BextT + (size_t)(n0 + row) * 128 + (size_t)part * 8));
    }
}

// ---------------- main GEMM ----------------
__global__ void __launch_bounds__(NTHREADS, 2)
gemm_kernel(const int* __restrict__ Wq, float* __restrict__ out) {
    extern __shared__ char smem[];
    uint32_t sb = smem_u32(smem);
    int tid  = threadIdx.x;
    int wid  = tid >> 5;          // 0..7
    int lane = tid & 31;
    int wm   = wid >> 2;          // 0..1 -> 64 m-rows
    int wn   = wid & 3;           // 0..3 -> 32 n-cols

    int n0 = blockIdx.x * TILE_N;
    int m0 = blockIdx.y * TILE_M;

    float acc[4][4][4];
#pragma unroll
    for (int tm = 0; tm < 4; tm++)
#pragma unroll
        for (int tn = 0; tn < 4; tn++)
#pragma unroll
            for (int c = 0; c < 4; c++) acc[tm][tn][c] = 0.f;

    // A ldmatrix lane addressing (272B padded rows: conflict-free)
    uint32_t offA[4];
#pragma unroll
    for (int tm = 0; tm < 4; tm++) {
        int rowA = wm * 64 + tm * 16 + (lane & 15);
        offA[tm] = (uint32_t)rowA * ROW_STRIDE + (uint32_t)(lane >> 4) * 16;
    }
    // n byte-offsets for packed W / sc reads: n(tn) = wn*32 + tn*8 + (lane>>2)
    uint32_t nb[4];
#pragma unroll
    for (int tn = 0; tn < 4; tn++)
        nb[tn] = (uint32_t)(wn * 32 + tn * 8 + (lane >> 2)) * 4;
    uint32_t psel = 0x0101u * (uint32_t)(lane & 3);   // replicate byte c into bytes 0,2

    // ---------------- prologue: stage chunk 0 ----------------
    cp_a(sb + OFF_A0, 0, m0, tid);
    cp_w(sb + OFF_W, 0, n0, tid, Wq);
    cp_sc(sb, 0, 0, n0, tid);
    CP_COMMIT();
    CP_WAIT0();
    __syncthreads();

    for (int g = 0; g < 32; g++) {
        uint32_t aBs = sb + ((g & 1) ? OFF_A1 : OFF_A0);
        uint32_t wBs = sb + OFF_W + (uint32_t)(g & 1) * 8192;
        int nxt = g + 1;

        // prefetch next chunk
        if (nxt < 32) {
            cp_a(sb + ((nxt & 1) ? OFF_A1 : OFF_A0), nxt, m0, tid);
            cp_w(sb + OFF_W + (uint32_t)(nxt & 1) * 8192, nxt, n0, tid, Wq);
            cp_sc(sb, nxt & 1, nxt, n0, tid);
        } else {
            cp_a_ext(sb + OFF_A0, m0, tid);     // ext A -> buf0 (g=31 uses buf1)
        }
        CP_COMMIT();

        // per-group scale regs
        uint32_t s2[4], c2[4];
#pragma unroll
        for (int tn = 0; tn < 4; tn++) {
            uint32_t sc;
            asm("ld.shared.b32 %0, [%1];" : "=r"(sc)
                : "r"(sb + OFF_S + (uint32_t)(g & 1) * 512 + nb[tn]));
            asm("prmt.b32 %0, %1, %1, 0x1010;" : "=r"(s2[tn]) : "r"(sc));
            asm("prmt.b32 %0, %1, %1, 0x3232;" : "=r"(c2[tn]) : "r"(sc));
        }

        // ---- compute: 8 k16 steps, B built in registers from packed nibbles ----
#pragma unroll
        for (int k16 = 0; k16 < 8; k16++) {
            uint32_t b[4][2];
#pragma unroll
            for (int tn = 0; tn < 4; tn++) {
                uint32_t w0, w1;
                asm("ld.shared.b32 %0, [%1];" : "=r"(w0)
                    : "r"(wBs + (uint32_t)(2 * k16) * 512 + nb[tn]));
                asm("ld.shared.b32 %0, [%1];" : "=r"(w1)
                    : "r"(wBs + (uint32_t)(2 * k16 + 1) * 512 + nb[tn]));
#pragma unroll
                for (int h = 0; h < 2; h++) {
                    uint32_t w = h ? w1 : w0;
                    uint32_t t, t2, v;
                    asm("prmt.b32 %0, %1, %1, %2;" : "=r"(t) : "r"(w), "r"(psel));
                    t2 = t >> 4;
                    // v = (t & 0xF) | 0x64006400
                    asm("lop3.b32 %0, %1, 0x0000000F, 0x64006400, 0xEA;" : "=r"(v) : "r"(t));
                    // v |= (t2 & 0x000F0000)
                    asm("lop3.b32 %0, %1, 0x000F0000, %2, 0xEA;" : "=r"(v) : "r"(t2), "r"(v));
                    // b = v * s + (-1024*s)  => nibble*s
                    __half2 hv = __hfma2(*(__half2*)&v, *(__half2*)&s2[tn], *(__half2*)&c2[tn]);
                    b[tn][h] = *(uint32_t*)&hv;
                }
            }
#pragma unroll
            for (int tm = 0; tm < 4; tm++) {
                uint32_t a[4];
                LDSM_X4(a[0], a[1], a[2], a[3], aBs + offA[tm] + (uint32_t)k16 * 32);
                MMA16816(acc[tm][0], a, b[0][0], b[0][1]);
                MMA16816(acc[tm][1], a, b[1][0], b[1][1]);
                MMA16816(acc[tm][2], a, b[2][0], b[2][1]);
                MMA16816(acc[tm][3], a, b[3][0], b[3][1]);
            }
        }

        CP_WAIT0();
        __syncthreads();
    }

    // ---------------- ext chunk: A(ext) in buf0, B_ext via LDSM from buf1 ----------------
    cp_b_ext(sb + OFF_A1, n0, tid);
    CP_COMMIT();
    CP_WAIT0();
    __syncthreads();
    {
        uint32_t offB[2];
#pragma unroll
        for (int j = 0; j < 2; j++) {
            int rowB = wn * 32 + j * 16 + ((lane >> 4) << 3) + (lane & 7);
            offB[j] = sb + OFF_A1 + (uint32_t)rowB * ROW_STRIDE + (uint32_t)((lane >> 3) & 1) * 16;
        }
#pragma unroll
        for (int k16 = 0; k16 < 8; k16++) {
            uint32_t ko = (uint32_t)k16 * 32;
            uint32_t b[8];
            LDSM_X4(b[0], b[1], b[2], b[3], offB[0] + ko);
            LDSM_X4(b[4], b[5], b[6], b[7], offB[1] + ko);
#pragma unroll
            for (int tm = 0; tm < 4; tm++) {
                uint32_t a[4];
                LDSM_X4(a[0], a[1], a[2], a[3], sb + OFF_A0 + offA[tm] + ko);
                MMA16816(acc[tm][0], a, b[0], b[1]);
                MMA16816(acc[tm][1], a, b[2], b[3]);
                MMA16816(acc[tm][2], a, b[4], b[5]);
                MMA16816(acc[tm][3], a, b[6], b[7]);
            }
        }
    }

    // ---- store output ----
#pragma unroll
    for (int tm = 0; tm < 4; tm++) {
        int r1 = m0 + wm * 64 + tm * 16 + (lane >> 2);
#pragma unroll
        for (int tn = 0; tn < 4; tn++) {
            int nc = n0 + wn * 32 + tn * 8 + (lane & 3) * 2;
            *(float2*)(out + (size_t)r1 * N_DIM + nc)       = make_float2(acc[tm][tn][0], acc[tm][tn][1]);
            *(float2*)(out + (size_t)(r1 + 8) * N_DIM + nc) = make_float2(acc[tm][tn][2], acc[tm][tn][3]);
        }
    }
}

// ---------------- launch ----------------
extern "C" void kernel_launch(void* const* d_in, const int* in_sizes, int n_in,
                              void* d_out, int out_size) {
    const float* x      = (const float*)d_in[0];
    const int*   Wq     = (const int*)d_in[1];
    const float* scales = (const float*)d_in[2];
    const float* zeros  = (const float*)d_in[3];
    float* out = (float*)d_out;

    cudaFuncSetAttribute(gemm_kernel, cudaFuncAttributeMaxDynamicSharedMemorySize, SMEM_BYTES);

    prep_kernel<<<(M_DIM * NG_DIM * 32) / 256, 256>>>(x);
    prep_ext_kernel<<<(M_DIM * NG_DIM) / 256, 256>>>();
    prep_zs_kernel<<<(NG_DIM * N_DIM + 255) / 256, 256>>>(scales, zeros);

    dim3 grid(NT, MT);
    gemm_kernel<<<grid, NTHREADS, SMEM_BYTES>>>(Wq, out);
}

// round 13
// speedup vs baseline: 1.3748x; 1.3748x over previous
#include <cuda_runtime.h>
#include <cuda_fp16.h>
#include <cstdint>

#define M_DIM 8192
#define K_DIM 4096
#define N_DIM 11008
#define NG_DIM 32
#define KP_DIM 512
#define KSTR 4224                 /* K + 128 ext columns */
#define CH_K 64                   /* k-halves per chunk */
#define NCH  (KSTR / CH_K)        /* 66 */

#define TILE_M 128
#define TILE_N 128
#define NT (N_DIM / TILE_N) /* 86 */
#define MT (M_DIM / TILE_M) /* 64 */
#define NTHREADS 256

// ---------------- scratch (static device arrays: allocation-free) ----------------
__device__ __half g_A[(size_t)M_DIM * KSTR];    // fp16(x) + 128 ext cols (S hi,hi,lo,lo)
__device__ float  g_S[NG_DIM * M_DIM];          // group sums of rounded x
__device__ __half g_WT[(size_t)N_DIM * KSTR];   // fp16(nib*s) transposed [n][k] + ext rows

// ---------------- smem: 2 x (A 16KB + B 16KB), 128 rows x 128B, XOR swizzled ----------------
#define OFF_A0 0
#define OFF_A1 16384
#define OFF_B0 32768
#define OFF_B1 49152
#define SMEM_BYTES 65536

// ---------------- helpers ----------------
__device__ __forceinline__ uint32_t smem_u32(const void* p) {
    uint32_t a;
    asm("{ .reg .u64 t; cvta.to.shared.u64 t, %1; cvt.u32.u64 %0, t; }" : "=r"(a) : "l"(p));
    return a;
}

#define CP_ASYNC16(dst, src) \
    asm volatile("cp.async.cg.shared.global [%0], [%1], 16;" :: "r"(dst), "l"(src))
#define CP_COMMIT() asm volatile("cp.async.commit_group;" ::: "memory")
#define CP_WAIT0()  asm volatile("cp.async.wait_group 0;" ::: "memory")

#define LDSM_X4(r0, r1, r2, r3, addr) \
    asm volatile("ldmatrix.sync.aligned.m8n8.x4.shared.b16 {%0,%1,%2,%3}, [%4];" \
                 : "=r"(r0), "=r"(r1), "=r"(r2), "=r"(r3) : "r"(addr))

#define MMA16816(d, a, b0v, b1v) \
    asm volatile("mma.sync.aligned.m16n8k16.row.col.f32.f16.f16.f32 " \
                 "{%0,%1,%2,%3}, {%4,%5,%6,%7}, {%8,%9}, {%0,%1,%2,%3};" \
                 : "+f"((d)[0]), "+f"((d)[1]), "+f"((d)[2]), "+f"((d)[3]) \
                 : "r"((a)[0]), "r"((a)[1]), "r"((a)[2]), "r"((a)[3]), \
                   "r"(b0v), "r"(b1v))

// ---------------- prep 1: round x to fp16 into g_A + group sums ----------------
__global__ void prep_kernel(const float* __restrict__ x) {
    int gwarp = (blockIdx.x * blockDim.x + threadIdx.x) >> 5;
    int lane  = threadIdx.x & 31;
    if (gwarp >= M_DIM * NG_DIM) return;
    int m = gwarp / NG_DIM;
    int g = gwarp % NG_DIM;
    const float* xr = x + (size_t)m * K_DIM + (size_t)g * 128;
    __half* ar = g_A + (size_t)m * KSTR + (size_t)g * 128;
    float sum = 0.f;
#pragma unroll
    for (int j = 0; j < 4; j++) {
        float v = xr[lane + 32 * j];
        __half hi = __float2half_rn(v);
        ar[lane + 32 * j] = hi;
        sum += __half2float(hi);
    }
#pragma unroll
    for (int o = 16; o > 0; o >>= 1) sum += __shfl_xor_sync(0xFFFFFFFFu, sum, o);
    if (lane == 0) g_S[g * M_DIM + m] = sum;
}

// ---------------- prep 2a: A extension cols (S hi,hi,lo,lo blocks) ----------------
__global__ void prep_ext_kernel() {
    int idx = blockIdx.x * blockDim.x + threadIdx.x;
    if (idx >= M_DIM * NG_DIM) return;
    int m = idx >> 5;
    int g = idx & 31;
    float S = g_S[g * M_DIM + m];
    __half hi = __float2half_rn(S);
    __half lo = __float2half_rn(S - __half2float(hi));
    __half* ar = g_A + (size_t)m * KSTR + 4096;
    ar[g]      = hi;
    ar[32 + g] = hi;
    ar[64 + g] = lo;
    ar[96 + g] = lo;
}

// ---------------- prep 2b: full dequant W -> fp16(nib*s) transposed [n][k] ----------------
__global__ void prep_w_kernel(const int* __restrict__ Wq, const float* __restrict__ scales) {
    int idx = blockIdx.x * blockDim.x + threadIdx.x;
    if (idx >= N_DIM * KP_DIM) return;
    int n  = idx >> 9;            // / 512
    int kp = idx & 511;
    uint32_t w = (uint32_t)Wq[(size_t)kp * N_DIM + n];
    float s = scales[(size_t)(kp >> 4) * N_DIM + n];
    __half h[8];
#pragma unroll
    for (int j = 0; j < 8; j++) {
        float v = (float)((w >> (4 * j)) & 15u);
        h[j] = __float2half_rn(v * s);     // single rounding of exact product
    }
    *(uint4*)(g_WT + (size_t)n * KSTR + (size_t)kp * 8) = *(uint4*)h;
}

// ---------------- prep 2c: ext B rows (zero-point term) into g_WT ----------------
__global__ void prep_zs_kernel(const float* __restrict__ scales, const float* __restrict__ zeros) {
    int idx = blockIdx.x * blockDim.x + threadIdx.x;
    if (idx >= NG_DIM * N_DIM) return;
    int g = idx / N_DIM;
    int n = idx - g * N_DIM;
    float zs = -zeros[idx] * scales[idx];
    __half hi = __float2half_rn(zs);
    __half lo = __float2half_rn(zs - __half2float(hi));
    __half* r = g_WT + (size_t)n * KSTR + 4096;
    r[g]      = hi;     // pairs with A ext col block [0,32)  = S_hi
    r[32 + g] = lo;     // pairs with S_hi
    r[64 + g] = hi;     // pairs with S_lo
    r[96 + g] = lo;     // pairs with S_lo  => total (S_hi+S_lo)*(zs_hi+zs_lo)
}

// ---------------- cp.async one 128x64-half chunk (16KB), XOR-swizzled ----------------
__device__ __forceinline__ void cp_chunk(uint32_t dbuf, const __half* __restrict__ gsrc,
                                         int row0, int ch, int tid) {
#pragma unroll
    for (int i = 0; i < 4; i++) {
        int idx = tid + i * NTHREADS;     // 0..1023 16B pieces
        int row = idx >> 3;
        int c   = idx & 7;
        const char* src = (const char*)(gsrc + (size_t)(row0 + row) * KSTR
                                        + (size_t)ch * CH_K + (size_t)c * 8);
        CP_ASYNC16(dbuf + (uint32_t)row * 128u + (uint32_t)((c ^ (row & 7)) << 4), src);
    }
}

// ---------------- main GEMM: plain fp16 double-buffered GEMM over K=4224 ----------------
__global__ void __launch_bounds__(NTHREADS, 2)
gemm_kernel(float* __restrict__ out) {
    extern __shared__ char smem[];
    uint32_t sb = smem_u32(smem);
    int tid  = threadIdx.x;
    int wid  = tid >> 5;          // 0..7
    int lane = tid & 31;
    int wm   = wid >> 2;          // 0..1 -> 64 m-rows
    int wn   = wid & 3;           // 0..3 -> 32 n-cols

    int n0 = blockIdx.x * TILE_N;
    int m0 = blockIdx.y * TILE_M;

    float acc[4][4][4];
#pragma unroll
    for (int tm = 0; tm < 4; tm++)
#pragma unroll
        for (int tn = 0; tn < 4; tn++)
#pragma unroll
            for (int c = 0; c < 4; c++) acc[tm][tn][c] = 0.f;

    // ldmatrix lane addressing (swizzled 128B rows)
    int s7 = lane & 7;
    int hA = lane >> 4;           // 0..1
    int hB = (lane >> 3) & 1;
    uint32_t offA[4];
#pragma unroll
    for (int tm = 0; tm < 4; tm++) {
        int rowA = wm * 64 + tm * 16 + (lane & 15);
        offA[tm] = (uint32_t)rowA * 128u;
    }
    uint32_t offB[2];
#pragma unroll
    for (int j = 0; j < 2; j++) {
        int rowB = wn * 32 + j * 16 + ((lane >> 4) << 3) + (lane & 7);
        offB[j] = (uint32_t)rowB * 128u;
    }

    // ---------------- prologue: chunk 0 ----------------
    cp_chunk(sb + OFF_A0, g_A, m0, 0, tid);
    cp_chunk(sb + OFF_B0, g_WT, n0, 0, tid);
    CP_COMMIT();
    CP_WAIT0();
    __syncthreads();

    for (int ch = 0; ch < NCH; ch++) {
        uint32_t aB = sb + ((ch & 1) ? OFF_A1 : OFF_A0);
        uint32_t bB = sb + ((ch & 1) ? OFF_B1 : OFF_B0);

        if (ch + 1 < NCH) {
            cp_chunk(sb + ((ch & 1) ? OFF_A0 : OFF_A1), g_A, m0, ch + 1, tid);
            cp_chunk(sb + ((ch & 1) ? OFF_B0 : OFF_B1), g_WT, n0, ch + 1, tid);
        }
        CP_COMMIT();

        // ---- compute: 4 k16 steps ----
#pragma unroll
        for (int k16 = 0; k16 < 4; k16++) {
            uint32_t b[8];
            uint32_t cB = (uint32_t)(((2 * k16 + hB) ^ s7) << 4);
            LDSM_X4(b[0], b[1], b[2], b[3], bB + offB[0] + cB);
            LDSM_X4(b[4], b[5], b[6], b[7], bB + offB[1] + cB);
            uint32_t cA = (uint32_t)(((2 * k16 + hA) ^ s7) << 4);
#pragma unroll
            for (int tm = 0; tm < 4; tm++) {
                uint32_t a[4];
                LDSM_X4(a[0], a[1], a[2], a[3], aB + offA[tm] + cA);
                MMA16816(acc[tm][0], a, b[0], b[1]);
                MMA16816(acc[tm][1], a, b[2], b[3]);
                MMA16816(acc[tm][2], a, b[4], b[5]);
                MMA16816(acc[tm][3], a, b[6], b[7]);
            }
        }

        CP_WAIT0();
        __syncthreads();
    }

    // ---- store output ----
#pragma unroll
    for (int tm = 0; tm < 4; tm++) {
        int r1 = m0 + wm * 64 + tm * 16 + (lane >> 2);
#pragma unroll
        for (int tn = 0; tn < 4; tn++) {
            int nc = n0 + wn * 32 + tn * 8 + (lane & 3) * 2;
            *(float2*)(out + (size_t)r1 * N_DIM + nc)       = make_float2(acc[tm][tn][0], acc[tm][tn][1]);
            *(float2*)(out + (size_t)(r1 + 8) * N_DIM + nc) = make_float2(acc[tm][tn][2], acc[tm][tn][3]);
        }
    }
}

// ---------------- launch ----------------
extern "C" void kernel_launch(void* const* d_in, const int* in_sizes, int n_in,
                              void* d_out, int out_size) {
    const float* x      = (const float*)d_in[0];
    const int*   Wq     = (const int*)d_in[1];
    const float* scales = (const float*)d_in[2];
    const float* zeros  = (const float*)d_in[3];
    float* out = (float*)d_out;

    cudaFuncSetAttribute(gemm_kernel, cudaFuncAttributeMaxDynamicSharedMemorySize, SMEM_BYTES);

    prep_kernel<<<(M_DIM * NG_DIM * 32) / 256, 256>>>(x);
    prep_ext_kernel<<<(M_DIM * NG_DIM) / 256, 256>>>();
    prep_w_kernel<<<(N_DIM * KP_DIM) / 256, 256>>>(Wq, scales);
    prep_zs_kernel<<<(NG_DIM * N_DIM + 255) / 256, 256>>>(scales, zeros);

    dim3 grid(NT, MT);
    gemm_kernel<<<grid, NTHREADS, SMEM_BYTES>>>(out);
}

// round 14
// speedup vs baseline: 1.3825x; 1.0056x over previous
#include <cuda_runtime.h>
#include <cuda_fp16.h>
#include <cstdint>

#define M_DIM 8192
#define K_DIM 4096
#define N_DIM 11008
#define NG_DIM 32
#define KP_DIM 512
#define KSTR 4224                 /* K + 128 ext columns */
#define CH_K 64                   /* k-halves per chunk */
#define NCH  (KSTR / CH_K)        /* 66 = 3 * 22 */

#define TILE_M 128
#define TILE_N 128
#define NT (N_DIM / TILE_N) /* 86 */
#define MT (M_DIM / TILE_M) /* 64 */
#define NTHREADS 256

// ---------------- scratch (static device arrays: allocation-free) ----------------
__device__ __half g_A[(size_t)M_DIM * KSTR];    // fp16(x) + 128 ext cols (S hi,hi,lo,lo)
__device__ __half g_WT[(size_t)N_DIM * KSTR];   // fp16(nib*s) transposed [n][k] + ext rows

// ---------------- smem: 3 stages x (A 16KB + B 16KB), 128B rows, XOR swizzled ----------------
#define STAGE_A(s) ((uint32_t)(s) * 16384u)
#define STAGE_B(s) (49152u + (uint32_t)(s) * 16384u)
#define SMEM_BYTES 98304

// ---------------- helpers ----------------
__device__ __forceinline__ uint32_t smem_u32(const void* p) {
    uint32_t a;
    asm("{ .reg .u64 t; cvta.to.shared.u64 t, %1; cvt.u32.u64 %0, t; }" : "=r"(a) : "l"(p));
    return a;
}

#define CP_ASYNC16(dst, src) \
    asm volatile("cp.async.cg.shared.global [%0], [%1], 16;" :: "r"(dst), "l"(src))
#define CP_COMMIT()  asm volatile("cp.async.commit_group;" ::: "memory")
#define CP_WAIT1()   asm volatile("cp.async.wait_group 1;" ::: "memory")

#define LDSM_X4(r0, r1, r2, r3, addr) \
    asm volatile("ldmatrix.sync.aligned.m8n8.x4.shared.b16 {%0,%1,%2,%3}, [%4];" \
                 : "=r"(r0), "=r"(r1), "=r"(r2), "=r"(r3) : "r"(addr))

#define MMA16816(d, a, b0v, b1v) \
    asm volatile("mma.sync.aligned.m16n8k16.row.col.f32.f16.f16.f32 " \
                 "{%0,%1,%2,%3}, {%4,%5,%6,%7}, {%8,%9}, {%0,%1,%2,%3};" \
                 : "+f"((d)[0]), "+f"((d)[1]), "+f"((d)[2]), "+f"((d)[3]) \
                 : "r"((a)[0]), "r"((a)[1]), "r"((a)[2]), "r"((a)[3]), \
                   "r"(b0v), "r"(b1v))

// ---------------- prep 1: round x to fp16 into g_A + ext cols (fused) ----------------
__global__ void prep_kernel(const float* __restrict__ x) {
    int gwarp = (blockIdx.x * blockDim.x + threadIdx.x) >> 5;
    int lane  = threadIdx.x & 31;
    if (gwarp >= M_DIM * NG_DIM) return;
    int m = gwarp / NG_DIM;
    int g = gwarp % NG_DIM;
    const float* xr = x + (size_t)m * K_DIM + (size_t)g * 128;
    __half* ar = g_A + (size_t)m * KSTR + (size_t)g * 128;
    float sum = 0.f;
#pragma unroll
    for (int j = 0; j < 4; j++) {
        float v = xr[lane + 32 * j];
        __half hi = __float2half_rn(v);
        ar[lane + 32 * j] = hi;
        sum += __half2float(hi);
    }
#pragma unroll
    for (int o = 16; o > 0; o >>= 1) sum += __shfl_xor_sync(0xFFFFFFFFu, sum, o);
    if (lane == 0) {
        __half hi = __float2half_rn(sum);
        __half lo = __float2half_rn(sum - __half2float(hi));
        __half* er = g_A + (size_t)m * KSTR + 4096;
        er[g]      = hi;
        er[32 + g] = hi;
        er[64 + g] = lo;
        er[96 + g] = lo;
    }
}

// ---------------- prep 2: dequant W -> fp16(nib*s) [n][k] + zs ext rows (fused) ----------------
__global__ void prep_w_kernel(const int* __restrict__ Wq, const float* __restrict__ scales,
                              const float* __restrict__ zeros) {
    int idx = blockIdx.x * blockDim.x + threadIdx.x;
    if (idx >= N_DIM * KP_DIM) return;
    int n  = idx >> 9;            // / 512
    int kp = idx & 511;
    uint32_t w = (uint32_t)Wq[(size_t)kp * N_DIM + n];
    float s = scales[(size_t)(kp >> 4) * N_DIM + n];
    __half h[8];
#pragma unroll
    for (int j = 0; j < 8; j++) {
        float v = (float)((w >> (4 * j)) & 15u);
        h[j] = __float2half_rn(v * s);     // single rounding of exact product
    }
    *(uint4*)(g_WT + (size_t)n * KSTR + (size_t)kp * 8) = *(uint4*)h;

    if (kp < 32) {                 // zero-point ext rows, g = kp
        int g = kp;
        float sg = scales[(size_t)g * N_DIM + n];
        float zs = -zeros[(size_t)g * N_DIM + n] * sg;
        __half hi = __float2half_rn(zs);
        __half lo = __float2half_rn(zs - __half2float(hi));
        __half* r = g_WT + (size_t)n * KSTR + 4096;
        r[g]      = hi;   // pairs with A ext (S_hi)
        r[32 + g] = lo;   // pairs with S_hi
        r[64 + g] = hi;   // pairs with S_lo
        r[96 + g] = lo;   // => (S_hi+S_lo)*(zs_hi+zs_lo)
    }
}

// ---------------- cp.async one 128x64-half chunk (16KB), XOR-swizzled ----------------
__device__ __forceinline__ void cp_chunk(uint32_t dbuf, const __half* __restrict__ gsrc,
                                         int row0, int ch, int tid) {
#pragma unroll
    for (int i = 0; i < 4; i++) {
        int idx = tid + i * NTHREADS;     // 0..1023 16B pieces
        int row = idx >> 3;
        int c   = idx & 7;
        const char* src = (const char*)(gsrc + (size_t)(row0 + row) * KSTR
                                        + (size_t)ch * CH_K + (size_t)c * 8);
        CP_ASYNC16(dbuf + (uint32_t)row * 128u + (uint32_t)((c ^ (row & 7)) << 4), src);
    }
}

// ---------------- main GEMM: fp16 GEMM over K=4224, 3-stage pipeline ----------------
__global__ void __launch_bounds__(NTHREADS, 2)
gemm_kernel(float* __restrict__ out) {
    extern __shared__ char smem[];
    uint32_t sb = smem_u32(smem);
    int tid  = threadIdx.x;
    int wid  = tid >> 5;          // 0..7
    int lane = tid & 31;
    int wm   = wid >> 2;          // 0..1 -> 64 m-rows
    int wn   = wid & 3;           // 0..3 -> 32 n-cols

    int n0 = blockIdx.x * TILE_N;
    int m0 = blockIdx.y * TILE_M;

    float acc[4][4][4];
#pragma unroll
    for (int tm = 0; tm < 4; tm++)
#pragma unroll
        for (int tn = 0; tn < 4; tn++)
#pragma unroll
            for (int c = 0; c < 4; c++) acc[tm][tn][c] = 0.f;

    // ldmatrix lane addressing (swizzled 128B rows)
    int s7 = lane & 7;
    int hA = lane >> 4;
    int hB = (lane >> 3) & 1;
    uint32_t offA[4];
#pragma unroll
    for (int tm = 0; tm < 4; tm++) {
        int rowA = wm * 64 + tm * 16 + (lane & 15);
        offA[tm] = (uint32_t)rowA * 128u;
    }
    uint32_t offB[2];
#pragma unroll
    for (int j = 0; j < 2; j++) {
        int rowB = wn * 32 + j * 16 + ((lane >> 4) << 3) + (lane & 7);
        offB[j] = (uint32_t)rowB * 128u;
    }

    // ---------------- prologue: stage chunks 0 and 1 ----------------
    cp_chunk(sb + STAGE_A(0), g_A, m0, 0, tid);
    cp_chunk(sb + STAGE_B(0), g_WT, n0, 0, tid);
    CP_COMMIT();
    cp_chunk(sb + STAGE_A(1), g_A, m0, 1, tid);
    cp_chunk(sb + STAGE_B(1), g_WT, n0, 1, tid);
    CP_COMMIT();

#define ITER(CH, SCUR, SNXT2)                                                      \
    do {                                                                           \
        CP_WAIT1();                                                                \
        __syncthreads();                                                           \
        if ((CH) + 2 < NCH) {                                                      \
            cp_chunk(sb + STAGE_A(SNXT2), g_A, m0, (CH) + 2, tid);                 \
            cp_chunk(sb + STAGE_B(SNXT2), g_WT, n0, (CH) + 2, tid);                \
        }                                                                          \
        CP_COMMIT();                                                               \
        uint32_t aB = sb + STAGE_A(SCUR);                                          \
        uint32_t bB = sb + STAGE_B(SCUR);                                          \
        _Pragma("unroll")                                                          \
        for (int k16 = 0; k16 < 4; k16++) {                                        \
            uint32_t b[8];                                                         \
            uint32_t cB = (uint32_t)(((2 * k16 + hB) ^ s7) << 4);                  \
            LDSM_X4(b[0], b[1], b[2], b[3], bB + offB[0] + cB);                    \
            LDSM_X4(b[4], b[5], b[6], b[7], bB + offB[1] + cB);                    \
            uint32_t cA = (uint32_t)(((2 * k16 + hA) ^ s7) << 4);                  \
            _Pragma("unroll")                                                      \
            for (int tm = 0; tm < 4; tm++) {                                       \
                uint32_t a[4];                                                     \
                LDSM_X4(a[0], a[1], a[2], a[3], aB + offA[tm] + cA);               \
                MMA16816(acc[tm][0], a, b[0], b[1]);                               \
                MMA16816(acc[tm][1], a, b[2], b[3]);                               \
                MMA16816(acc[tm][2], a, b[4], b[5]);                               \
                MMA16816(acc[tm][3], a, b[6], b[7]);                               \
            }                                                                      \
        }                                                                          \
    } while (0)

    for (int ch = 0; ch < NCH; ch += 3) {
        ITER(ch,     0, 2);
        ITER(ch + 1, 1, 0);
        ITER(ch + 2, 2, 1);
    }
#undef ITER

    // ---- store output ----
#pragma unroll
    for (int tm = 0; tm < 4; tm++) {
        int r1 = m0 + wm * 64 + tm * 16 + (lane >> 2);
#pragma unroll
        for (int tn = 0; tn < 4; tn++) {
            int nc = n0 + wn * 32 + tn * 8 + (lane & 3) * 2;
            *(float2*)(out + (size_t)r1 * N_DIM + nc)       = make_float2(acc[tm][tn][0], acc[tm][tn][1]);
            *(float2*)(out + (size_t)(r1 + 8) * N_DIM + nc) = make_float2(acc[tm][tn][2], acc[tm][tn][3]);
        }
    }
}

// ---------------- launch ----------------
extern "C" void kernel_launch(void* const* d_in, const int* in_sizes, int n_in,
                              void* d_out, int out_size) {
    const float* x      = (const float*)d_in[0];
    const int*   Wq     = (const int*)d_in[1];
    const float* scales = (const float*)d_in[2];
    const float* zeros  = (const float*)d_in[3];
    float* out = (float*)d_out;

    cudaFuncSetAttribute(gemm_kernel, cudaFuncAttributeMaxDynamicSharedMemorySize, SMEM_BYTES);

    prep_kernel<<<(M_DIM * NG_DIM * 32) / 256, 256>>>(x);
    prep_w_kernel<<<(N_DIM * KP_DIM) / 256, 256>>>(Wq, scales, zeros);

    dim3 grid(NT, MT);
    gemm_kernel<<<grid, NTHREADS, SMEM_BYTES>>>(out);
}